// round 2
// baseline (speedup 1.0000x reference)
#include <cuda_runtime.h>

#define B_ 4
#define N_ 4096
#define C_ 512
#define D_ 64

// Scratch (no allocations allowed) — q,k: [B*N, 64]; v: [B*N, 512]
__device__ float g_q[(size_t)B_ * N_ * D_];
__device__ float g_k[(size_t)B_ * N_ * D_];
__device__ float g_v[(size_t)B_ * N_ * C_];

// ---------------------------------------------------------------------------
// Tiled SGEMM: C[M, Ncols] = A[M, 512] @ B[512, Ncols], row-major.
// BM=128, BN=64, BK=16; 256 threads; each thread computes an 8x4 microtile.
// ---------------------------------------------------------------------------
#define GBM 128
#define GBN 64
#define GBK 16

__global__ __launch_bounds__(256) void sgemm_kernel(
    const float* __restrict__ A, const float* __restrict__ Bm,
    float* __restrict__ Cm, int Ncols) {
  __shared__ float As[GBK][GBM + 1];  // stored transposed (k-major rows)
  __shared__ float Bs[GBK][GBN];

  const int K = C_;
  const int tid = threadIdx.x;
  const int tr = tid >> 4;   // 0..15
  const int tc = tid & 15;   // 0..15
  const int m0 = blockIdx.y * GBM;
  const int n0 = blockIdx.x * GBN;

  float acc[8][4];
#pragma unroll
  for (int i = 0; i < 8; ++i)
#pragma unroll
    for (int j = 0; j < 4; ++j) acc[i][j] = 0.f;

  for (int k0 = 0; k0 < K; k0 += GBK) {
    // Load A tile [128 x 16] (transposed into As)
#pragma unroll
    for (int u = 0; u < 2; ++u) {
      int f = tid + u * 256;
      int row = f >> 2;
      int c4 = (f & 3) << 2;
      float4 a = *(const float4*)&A[(size_t)(m0 + row) * K + k0 + c4];
      As[c4 + 0][row] = a.x;
      As[c4 + 1][row] = a.y;
      As[c4 + 2][row] = a.z;
      As[c4 + 3][row] = a.w;
    }
    // Load B tile [16 x 64]
    {
      int row = tid >> 4;
      int c4 = (tid & 15) << 2;
      float4 b = *(const float4*)&Bm[(size_t)(k0 + row) * Ncols + n0 + c4];
      Bs[row][c4 + 0] = b.x;
      Bs[row][c4 + 1] = b.y;
      Bs[row][c4 + 2] = b.z;
      Bs[row][c4 + 3] = b.w;
    }
    __syncthreads();

#pragma unroll
    for (int kk = 0; kk < GBK; ++kk) {
      float ar[8], br[4];
#pragma unroll
      for (int i = 0; i < 8; ++i) ar[i] = As[kk][tr * 8 + i];
#pragma unroll
      for (int j = 0; j < 4; ++j) br[j] = Bs[kk][tc * 4 + j];
#pragma unroll
      for (int i = 0; i < 8; ++i)
#pragma unroll
        for (int j = 0; j < 4; ++j) acc[i][j] += ar[i] * br[j];
    }
    __syncthreads();
  }

#pragma unroll
  for (int i = 0; i < 8; ++i) {
    int row = m0 + tr * 8 + i;
    float4 r = make_float4(acc[i][0], acc[i][1], acc[i][2], acc[i][3]);
    *(float4*)&Cm[(size_t)row * Ncols + n0 + tc * 4] = r;
  }
}

// ---------------------------------------------------------------------------
// Fused flash attention (fp32):
//   S[i,j] = k_i . q_j, softmax over j, O[i,:] = sum_j P[i,j] * v[j,:]
//   out = gamma * O / l
// CTA: one (batch, 32-row i-tile), full C=512 in registers.
// 256 threads: ty = tid/64 (0..3), tx = tid%64 (0..63).
// Thread owns O rows ty*8..ty*8+7 and columns {tx*4..tx*4+3, 256+tx*4..+3}
// (split halves -> conflict-free LDS.128 on V: 16B thread stride).
// j streamed in tiles of 64; V staged 8 rows at a time through smem that is
// unioned with the Q tile buffer (Q is dead once S is computed).
// ---------------------------------------------------------------------------
__global__ __launch_bounds__(256, 2) void flash_kernel(
    const float* __restrict__ q, const float* __restrict__ k,
    const float* __restrict__ v, const float* __restrict__ gamma,
    float* __restrict__ out) {
  __shared__ float Ks[32][64];                 // k rows of this i-tile
  __shared__ __align__(16) float QV[64 * 65];  // union: Qs[64][65] / Vs[8][512]
  __shared__ float Ps[32][64];                 // S then P
  __shared__ float m_s[32], l_s[32], a_s[32];

  const int tid = threadIdx.x;
  const int ty = tid >> 6;  // 0..3
  const int tx = tid & 63;  // 0..63
  const int b = blockIdx.y;
  const int i0 = blockIdx.x * 32;

  // Load Ks: 32 x 64
#pragma unroll
  for (int u = 0; u < 2; ++u) {
    int f = tid + u * 256;
    int row = f >> 4;
    int c4 = (f & 15) << 2;
    float4 t = *(const float4*)&k[((size_t)b * N_ + i0 + row) * D_ + c4];
    *(float4*)&Ks[row][c4] = t;
  }
  if (tid < 32) {
    m_s[tid] = -3.0e38f;
    l_s[tid] = 0.f;
  }

  float o[8][8];  // [rr][0..3] = cols tx*4..+3 ; [rr][4..7] = cols 256+tx*4..+3
#pragma unroll
  for (int rr = 0; rr < 8; ++rr)
#pragma unroll
    for (int cc = 0; cc < 8; ++cc) o[rr][cc] = 0.f;

  __syncthreads();

  for (int j0 = 0; j0 < N_; j0 += 64) {
    // ---- Load Qs (64 x 64, padded to 65 for conflict-free column reads) ----
#pragma unroll
    for (int u = 0; u < 4; ++u) {
      int f = tid + u * 256;
      int row = f >> 4;
      int c4 = (f & 15) << 2;
      float4 t = *(const float4*)&q[((size_t)b * N_ + j0 + row) * D_ + c4];
      float* p = &QV[row * 65 + c4];
      p[0] = t.x;
      p[1] = t.y;
      p[2] = t.z;
      p[3] = t.w;
    }
    __syncthreads();

    // ---- S = Ks @ Qs^T; thread computes S[ty*8+rr][tx] ----
    float sac[8];
#pragma unroll
    for (int rr = 0; rr < 8; ++rr) sac[rr] = 0.f;
#pragma unroll 8
    for (int kd = 0; kd < 64; ++kd) {
      float qv = QV[tx * 65 + kd];
#pragma unroll
      for (int rr = 0; rr < 8; ++rr) sac[rr] += Ks[ty * 8 + rr][kd] * qv;
    }
#pragma unroll
    for (int rr = 0; rr < 8; ++rr) Ps[ty * 8 + rr][tx] = sac[rr];
    __syncthreads();

    // ---- Row max + rescale factor ----
    if (tid < 32) {
      float mo = m_s[tid];
      float mx = mo;
#pragma unroll 8
      for (int c = 0; c < 64; ++c) mx = fmaxf(mx, Ps[tid][c]);
      m_s[tid] = mx;
      a_s[tid] = __expf(mo - mx);
    }
    __syncthreads();

    // ---- exp + O rescale ----
#pragma unroll
    for (int rr = 0; rr < 8; ++rr) {
      int row = ty * 8 + rr;
      float p = __expf(sac[rr] - m_s[row]);
      Ps[row][tx] = p;
      float al = a_s[row];
#pragma unroll
      for (int cc = 0; cc < 8; ++cc) o[rr][cc] *= al;
    }
    __syncthreads();

    // ---- l update (reads Ps; safe to overlap with V staging below) ----
    if (tid < 32) {
      float s = 0.f;
#pragma unroll 8
      for (int c = 0; c < 64; ++c) s += Ps[tid][c];
      l_s[tid] = l_s[tid] * a_s[tid] + s;
    }

    // ---- PV: stage V 8 rows (x512 cols) at a time into the QV union ----
    for (int st = 0; st < 8; ++st) {
#pragma unroll
      for (int u = 0; u < 4; ++u) {
        int f = tid + u * 256;
        int row = f >> 7;          // 0..7
        int c4 = (f & 127) << 2;   // 0..508
        float4 t =
            *(const float4*)&v[((size_t)b * N_ + j0 + st * 8 + row) * C_ + c4];
        *(float4*)&QV[row * 512 + c4] = t;
      }
      __syncthreads();
#pragma unroll
      for (int kk = 0; kk < 8; ++kk) {
        // 16B thread stride -> conflict-free LDS.128 in each quarter-warp phase
        float4 v0 = *(const float4*)&QV[kk * 512 + tx * 4];
        float4 v1 = *(const float4*)&QV[kk * 512 + 256 + tx * 4];
#pragma unroll
        for (int rr = 0; rr < 8; ++rr) {
          float p = Ps[ty * 8 + rr][st * 8 + kk];
          o[rr][0] += p * v0.x;
          o[rr][1] += p * v0.y;
          o[rr][2] += p * v0.z;
          o[rr][3] += p * v0.w;
          o[rr][4] += p * v1.x;
          o[rr][5] += p * v1.y;
          o[rr][6] += p * v1.z;
          o[rr][7] += p * v1.w;
        }
      }
      __syncthreads();
    }
  }

  // ---- Epilogue: out = gamma * O / l ----
  const float gm = gamma[0];
#pragma unroll
  for (int rr = 0; rr < 8; ++rr) {
    int row = ty * 8 + rr;
    float inv = gm / l_s[row];
    float4 r0 = make_float4(o[rr][0] * inv, o[rr][1] * inv, o[rr][2] * inv,
                            o[rr][3] * inv);
    float4 r1 = make_float4(o[rr][4] * inv, o[rr][5] * inv, o[rr][6] * inv,
                            o[rr][7] * inv);
    size_t base = ((size_t)b * N_ + i0 + row) * C_;
    *(float4*)&out[base + tx * 4] = r0;
    *(float4*)&out[base + 256 + tx * 4] = r1;
  }
}

// ---------------------------------------------------------------------------
extern "C" void kernel_launch(void* const* d_in, const int* in_sizes, int n_in,
                              void* d_out, int out_size) {
  const float* x = (const float*)d_in[0];
  const float* Wq = (const float*)d_in[1];
  const float* Wk = (const float*)d_in[2];
  const float* Wv = (const float*)d_in[3];
  const float* gamma = (const float*)d_in[4];
  float* out = (float*)d_out;

  float *qp, *kp, *vp;
  cudaGetSymbolAddress((void**)&qp, g_q);
  cudaGetSymbolAddress((void**)&kp, g_k);
  cudaGetSymbolAddress((void**)&vp, g_v);

  dim3 gqk(D_ / GBN, (B_ * N_) / GBM);  // (1, 128)
  sgemm_kernel<<<gqk, 256>>>(x, Wq, qp, D_);
  sgemm_kernel<<<gqk, 256>>>(x, Wk, kp, D_);

  dim3 gv(C_ / GBN, (B_ * N_) / GBM);  // (8, 128)
  sgemm_kernel<<<gv, 256>>>(x, Wv, vp, C_);

  dim3 gf(N_ / 32, B_);  // (128, 4)
  flash_kernel<<<gf, 256>>>(qp, kp, vp, gamma, out);
}

// round 10
// speedup vs baseline: 2.9207x; 2.9207x over previous
#include <cuda_runtime.h>
#include <cuda_bf16.h>
#include <cstdint>

#define B_ 4
#define N_ 4096
#define C_ 512
#define D_ 64
#define BN_ (B_ * N_)

__device__ float g_q[(size_t)BN_ * D_];
__device__ float g_k[(size_t)BN_ * D_];
__device__ float g_v[(size_t)BN_ * C_];
__device__ float g_e[(size_t)BN_ * N_];
__device__ float g_scale[BN_];
__device__ __nv_bfloat16 g_qh[(size_t)BN_ * D_], g_ql[(size_t)BN_ * D_];
__device__ __nv_bfloat16 g_kh[(size_t)BN_ * D_], g_kl[(size_t)BN_ * D_];
__device__ __nv_bfloat16 g_vth[(size_t)C_ * BN_], g_vtl[(size_t)C_ * BN_];
__device__ __nv_bfloat16 g_ph[(size_t)BN_ * N_], g_pl[(size_t)BN_ * N_];

__device__ __forceinline__ uint32_t smem_u32(const void* p) {
  uint32_t a;
  asm("{ .reg .u64 t; cvta.to.shared.u64 t, %1; cvt.u32.u64 %0, t; }" : "=r"(a) : "l"(p));
  return a;
}
__device__ __forceinline__ void split2(float v, __nv_bfloat16& h, __nv_bfloat16& l) {
  h = __float2bfloat16(v);
  l = __float2bfloat16(v - __bfloat162float(h));
}

#define CP16(d, s) asm volatile("cp.async.cg.shared.global [%0], [%1], 16;" :: "r"(d), "l"(s))
#define CPCOMMIT() asm volatile("cp.async.commit_group;" ::: "memory")
#define CPWAIT1() asm volatile("cp.async.wait_group 1;" ::: "memory")

__device__ __forceinline__ void ldsm4(uint32_t* r, uint32_t a) {
  asm volatile("ldmatrix.sync.aligned.m8n8.x4.shared.b16 {%0,%1,%2,%3}, [%4];"
               : "=r"(r[0]), "=r"(r[1]), "=r"(r[2]), "=r"(r[3]) : "r"(a));
}
__device__ __forceinline__ void mma16816(float* d, const uint32_t* a, const uint32_t* b) {
  asm volatile(
      "mma.sync.aligned.m16n8k16.row.col.f32.bf16.bf16.f32 "
      "{%0,%1,%2,%3}, {%4,%5,%6,%7}, {%8,%9}, {%0,%1,%2,%3};"
      : "+f"(d[0]), "+f"(d[1]), "+f"(d[2]), "+f"(d[3])
      : "r"(a[0]), "r"(a[1]), "r"(a[2]), "r"(a[3]), "r"(b[0]), "r"(b[1]));
}

// ---------------- SIMT projection GEMM (proven in R2) ----------------------
__global__ __launch_bounds__(256) void sgemm_kernel(const float* __restrict__ A,
                                                    const float* __restrict__ Bm,
                                                    float* __restrict__ Cm, int Ncols) {
  __shared__ float As[16][129];
  __shared__ float Bs[16][64];
  const int tid = threadIdx.x, tr = tid >> 4, tc = tid & 15;
  const int m0 = blockIdx.y * 128, n0 = blockIdx.x * 64;
  float acc[8][4];
#pragma unroll
  for (int i = 0; i < 8; ++i)
#pragma unroll
    for (int j = 0; j < 4; ++j) acc[i][j] = 0.f;
  for (int k0 = 0; k0 < C_; k0 += 16) {
#pragma unroll
    for (int u = 0; u < 2; ++u) {
      int f = tid + u * 256, row = f >> 2, c4 = (f & 3) << 2;
      float4 a = *(const float4*)&A[(size_t)(m0 + row) * C_ + k0 + c4];
      As[c4][row] = a.x; As[c4 + 1][row] = a.y; As[c4 + 2][row] = a.z; As[c4 + 3][row] = a.w;
    }
    {
      int row = tid >> 4, c4 = (tid & 15) << 2;
      float4 b = *(const float4*)&Bm[(size_t)(k0 + row) * Ncols + n0 + c4];
      Bs[row][c4] = b.x; Bs[row][c4 + 1] = b.y; Bs[row][c4 + 2] = b.z; Bs[row][c4 + 3] = b.w;
    }
    __syncthreads();
#pragma unroll
    for (int kk = 0; kk < 16; ++kk) {
      float ar[8], br[4];
#pragma unroll
      for (int i = 0; i < 8; ++i) ar[i] = As[kk][tr * 8 + i];
#pragma unroll
      for (int j = 0; j < 4; ++j) br[j] = Bs[kk][tc * 4 + j];
#pragma unroll
      for (int i = 0; i < 8; ++i)
#pragma unroll
        for (int j = 0; j < 4; ++j) acc[i][j] += ar[i] * br[j];
    }
    __syncthreads();
  }
#pragma unroll
  for (int i = 0; i < 8; ++i)
    *(float4*)&Cm[(size_t)(m0 + tr * 8 + i) * Ncols + n0 + tc * 4] =
        make_float4(acc[i][0], acc[i][1], acc[i][2], acc[i][3]);
}

__global__ __launch_bounds__(256) void split_kernel(const float* __restrict__ s,
                                                    __nv_bfloat16* __restrict__ h,
                                                    __nv_bfloat16* __restrict__ l, int n4) {
  int i = blockIdx.x * 256 + threadIdx.x;
  if (i >= n4) return;
  float4 v = ((const float4*)s)[i];
  __nv_bfloat16 h0, h1, h2, h3, l0, l1, l2, l3;
  split2(v.x, h0, l0); split2(v.y, h1, l1); split2(v.z, h2, l2); split2(v.w, h3, l3);
  ((__nv_bfloat162*)h)[i * 2] = __nv_bfloat162(h0, h1);
  ((__nv_bfloat162*)h)[i * 2 + 1] = __nv_bfloat162(h2, h3);
  ((__nv_bfloat162*)l)[i * 2] = __nv_bfloat162(l0, l1);
  ((__nv_bfloat162*)l)[i * 2 + 1] = __nv_bfloat162(l2, l3);
}

// V [n, c] f32 -> Vt hi/lo [c][n] bf16
__global__ __launch_bounds__(256) void transpose_split_v(const float* __restrict__ v,
                                                         __nv_bfloat16* __restrict__ th,
                                                         __nv_bfloat16* __restrict__ tl) {
  __shared__ float T[64][65];
  const int tid = threadIdx.x, n0 = blockIdx.x * 64, c0 = blockIdx.y * 64;
#pragma unroll
  for (int u = 0; u < 4; ++u) {
    int f = tid + u * 256, r = f >> 4, c4 = (f & 15) << 2;
    float4 t = *(const float4*)&v[(size_t)(n0 + r) * C_ + c0 + c4];
    T[r][c4] = t.x; T[r][c4 + 1] = t.y; T[r][c4 + 2] = t.z; T[r][c4 + 3] = t.w;
  }
  __syncthreads();
#pragma unroll
  for (int u = 0; u < 4; ++u) {
    int f = tid + u * 256, c = f >> 4, n4 = (f & 15) << 2;
    __nv_bfloat16 h[4], l[4];
#pragma unroll
    for (int i = 0; i < 4; ++i) split2(T[n4 + i][c], h[i], l[i]);
    size_t o = ((size_t)(c0 + c) * BN_ + n0 + n4) >> 1;
    ((__nv_bfloat162*)th)[o] = __nv_bfloat162(h[0], h[1]);
    ((__nv_bfloat162*)th)[o + 1] = __nv_bfloat162(h[2], h[3]);
    ((__nv_bfloat162*)tl)[o] = __nv_bfloat162(l[0], l[1]);
    ((__nv_bfloat162*)tl)[o + 1] = __nv_bfloat162(l[2], l[3]);
  }
}

// ---------------------------------------------------------------------------
// Generic split-bf16 GEMM via mma.sync: C[128x128 tile] = A . B^T, row.col.
// A rows: (b*N_ + i0 + r) * lda ; B rows: (n0 + r) * ldb + b * bStrB.
// 8 warps: warp tile m64 x n32 (wm = wid&1, wn = wid>>1).
// K chunks of 32, 2-stage cp.async double buffer (64KB dynamic smem).
// smem per stage: Ah(8K) Al(8K) Bh(8K) Bl(8K); 64B rows; 16B-chunk XOR swizzle
// (chunk ^= (row>>1)&3) -> conflict-free ldmatrix & cp.async phases.
// ---------------------------------------------------------------------------
__global__ __launch_bounds__(256) void mma_gemm(
    const __nv_bfloat16* __restrict__ Ah, const __nv_bfloat16* __restrict__ Al,
    const __nv_bfloat16* __restrict__ Bh, const __nv_bfloat16* __restrict__ Bl,
    float* __restrict__ Cm, const float* __restrict__ scale,
    int lda, int ldb, int ldc, int K, size_t bStrB) {
  extern __shared__ char dsm[];
  const uint32_t sb = smem_u32(dsm);
  const int tid = threadIdx.x, lane = tid & 31, wid = tid >> 5;
  const int wm = wid & 1, wn = wid >> 1;
  const int b = blockIdx.z;
  const int i0 = blockIdx.x * 128, n0 = blockIdx.y * 128;
  const size_t bN = (size_t)b * N_;

  float acc[4][4][4];
#pragma unroll
  for (int mi = 0; mi < 4; ++mi)
#pragma unroll
    for (int nj = 0; nj < 4; ++nj)
#pragma unroll
      for (int e = 0; e < 4; ++e) acc[mi][nj][e] = 0.f;

  auto issue = [&](int kc) {
#pragma unroll
    for (int t = 0; t < 8; ++t) {
      int g = tid + t * 256, sub = g >> 9, gi = g & 511, row = gi >> 2, cc = gi & 3;
      uint32_t so = sb + (uint32_t)((kc & 1) * 32768 + sub * 8192 + row * 64 +
                                    ((cc ^ ((row >> 1) & 3)) << 4));
      const __nv_bfloat16* gp;
      if (sub < 2)
        gp = (sub == 0 ? Ah : Al) + (bN + i0 + row) * (size_t)lda + kc * 32 + cc * 8;
      else
        gp = (sub == 2 ? Bh : Bl) + (size_t)(n0 + row) * ldb + (size_t)b * bStrB +
             kc * 32 + cc * 8;
      CP16(so, gp);
    }
    CPCOMMIT();
  };

  const int chunks = K >> 5;
  issue(0);
  for (int kc = 0; kc < chunks; ++kc) {
    if (kc + 1 < chunks) issue(kc + 1); else CPCOMMIT();
    CPWAIT1();
    __syncthreads();
    const uint32_t st = sb + (uint32_t)((kc & 1) * 32768);
#pragma unroll
    for (int ks = 0; ks < 32; ks += 16) {
      uint32_t ah[4][4], al[4][4], bh[8], bl[8];
      const int rA = lane & 15, cA = (ks >> 3) + (lane >> 4);
      const int rB = (lane & 7) + ((lane >> 4) << 3), cB = (ks >> 3) + ((lane >> 3) & 1);
#pragma unroll
      for (int mi = 0; mi < 4; ++mi) {
        int row = wm * 64 + mi * 16 + rA;
        ldsm4(ah[mi], st + row * 64 + ((cA ^ ((row >> 1) & 3)) << 4));
      }
#pragma unroll
      for (int bf = 0; bf < 2; ++bf) {
        int row = wn * 32 + bf * 16 + rB;
        ldsm4(&bh[bf * 4], st + 16384 + row * 64 + ((cB ^ ((row >> 1) & 3)) << 4));
      }
#pragma unroll
      for (int mi = 0; mi < 4; ++mi)
#pragma unroll
        for (int nj = 0; nj < 4; ++nj) mma16816(acc[mi][nj], ah[mi], &bh[nj * 2]);
#pragma unroll
      for (int bf = 0; bf < 2; ++bf) {
        int row = wn * 32 + bf * 16 + rB;
        ldsm4(&bl[bf * 4], st + 24576 + row * 64 + ((cB ^ ((row >> 1) & 3)) << 4));
      }
#pragma unroll
      for (int mi = 0; mi < 4; ++mi)
#pragma unroll
        for (int nj = 0; nj < 4; ++nj) mma16816(acc[mi][nj], ah[mi], &bl[nj * 2]);
#pragma unroll
      for (int mi = 0; mi < 4; ++mi) {
        int row = wm * 64 + mi * 16 + rA;
        ldsm4(al[mi], st + 8192 + row * 64 + ((cA ^ ((row >> 1) & 3)) << 4));
      }
#pragma unroll
      for (int mi = 0; mi < 4; ++mi)
#pragma unroll
        for (int nj = 0; nj < 4; ++nj) mma16816(acc[mi][nj], al[mi], &bh[nj * 2]);
    }
    __syncthreads();
  }

#pragma unroll
  for (int mi = 0; mi < 4; ++mi) {
    int r0 = i0 + wm * 64 + mi * 16 + (lane >> 2);
    float s0 = scale ? scale[bN + r0] : 1.f;
    float s1 = scale ? scale[bN + r0 + 8] : 1.f;
#pragma unroll
    for (int nj = 0; nj < 4; ++nj) {
      int col = n0 + wn * 32 + nj * 8 + 2 * (lane & 3);
      float2 v0 = {acc[mi][nj][0] * s0, acc[mi][nj][1] * s0};
      float2 v1 = {acc[mi][nj][2] * s1, acc[mi][nj][3] * s1};
      *(float2*)&Cm[(bN + r0) * (size_t)ldc + col] = v0;
      *(float2*)&Cm[(bN + r0 + 8) * (size_t)ldc + col] = v1;
    }
  }
}

// K2: row softmax -> split-bf16 P, scale = gamma / rowsum
__global__ __launch_bounds__(256) void softmax_kernel(const float* __restrict__ E,
                                                      __nv_bfloat16* __restrict__ ph,
                                                      __nv_bfloat16* __restrict__ pl,
                                                      float* __restrict__ scale,
                                                      const float* __restrict__ gamma) {
  __shared__ float row[N_];
  __shared__ float red[8];
  __shared__ float bc;
  const int tid = threadIdx.x, wid = tid >> 5, lid = tid & 31;
  const size_t r = blockIdx.x;
  const float* er = E + r * N_;
  float lmax = -3.0e38f;
#pragma unroll
  for (int u = 0; u < 4; ++u) {
    int idx = tid + u * 256;
    float4 t = ((const float4*)er)[idx];
    ((float4*)row)[idx] = t;
    lmax = fmaxf(lmax, fmaxf(fmaxf(t.x, t.y), fmaxf(t.z, t.w)));
  }
#pragma unroll
  for (int s = 16; s > 0; s >>= 1) lmax = fmaxf(lmax, __shfl_xor_sync(~0u, lmax, s));
  if (lid == 0) red[wid] = lmax;
  __syncthreads();
  if (tid == 0) {
    float m = red[0];
#pragma unroll
    for (int i = 1; i < 8; ++i) m = fmaxf(m, red[i]);
    bc = m;
  }
  __syncthreads();
  const float m = bc;
  float lsum = 0.f;
#pragma unroll
  for (int u = 0; u < 4; ++u) {
    int idx = tid + u * 256;
    float4 t = ((const float4*)row)[idx];
    float p0 = __expf(t.x - m), p1 = __expf(t.y - m), p2 = __expf(t.z - m), p3 = __expf(t.w - m);
    lsum += (p0 + p1) + (p2 + p3);
    __nv_bfloat16 h0, h1, h2, h3, l0, l1, l2, l3;
    split2(p0, h0, l0); split2(p1, h1, l1); split2(p2, h2, l2); split2(p3, h3, l3);
    size_t o = (r * N_ + (size_t)idx * 4) >> 1;
    ((__nv_bfloat162*)ph)[o] = __nv_bfloat162(h0, h1);
    ((__nv_bfloat162*)ph)[o + 1] = __nv_bfloat162(h2, h3);
    ((__nv_bfloat162*)pl)[o] = __nv_bfloat162(l0, l1);
    ((__nv_bfloat162*)pl)[o + 1] = __nv_bfloat162(l2, l3);
  }
#pragma unroll
  for (int s = 16; s > 0; s >>= 1) lsum += __shfl_xor_sync(~0u, lsum, s);
  if (lid == 0) red[wid] = lsum;
  __syncthreads();
  if (tid == 0) {
    float t = 0.f;
#pragma unroll
    for (int i = 0; i < 8; ++i) t += red[i];
    scale[r] = gamma[0] / t;
  }
}

extern "C" void kernel_launch(void* const* d_in, const int* in_sizes, int n_in,
                              void* d_out, int out_size) {
  const float* x = (const float*)d_in[0];
  const float* Wq = (const float*)d_in[1];
  const float* Wk = (const float*)d_in[2];
  const float* Wv = (const float*)d_in[3];
  const float* gamma = (const float*)d_in[4];
  float* out = (float*)d_out;

  float *qp, *kp, *vp, *ep, *scp;
  __nv_bfloat16 *qh, *ql, *kh, *kl, *vth, *vtl, *ph, *pl;
  cudaGetSymbolAddress((void**)&qp, g_q);
  cudaGetSymbolAddress((void**)&kp, g_k);
  cudaGetSymbolAddress((void**)&vp, g_v);
  cudaGetSymbolAddress((void**)&ep, g_e);
  cudaGetSymbolAddress((void**)&scp, g_scale);
  cudaGetSymbolAddress((void**)&qh, g_qh);
  cudaGetSymbolAddress((void**)&ql, g_ql);
  cudaGetSymbolAddress((void**)&kh, g_kh);
  cudaGetSymbolAddress((void**)&kl, g_kl);
  cudaGetSymbolAddress((void**)&vth, g_vth);
  cudaGetSymbolAddress((void**)&vtl, g_vtl);
  cudaGetSymbolAddress((void**)&ph, g_ph);
  cudaGetSymbolAddress((void**)&pl, g_pl);

  cudaFuncSetAttribute(mma_gemm, cudaFuncAttributeMaxDynamicSharedMemorySize, 65536);

  dim3 gqk(1, BN_ / 128);
  sgemm_kernel<<<gqk, 256>>>(x, Wq, qp, D_);
  sgemm_kernel<<<gqk, 256>>>(x, Wk, kp, D_);
  dim3 gv(C_ / 64, BN_ / 128);
  sgemm_kernel<<<gv, 256>>>(x, Wv, vp, C_);

  split_kernel<<<BN_ * D_ / 4 / 256, 256>>>(qp, qh, ql, BN_ * D_ / 4);
  split_kernel<<<BN_ * D_ / 4 / 256, 256>>>(kp, kh, kl, BN_ * D_ / 4);
  transpose_split_v<<<dim3(BN_ / 64, C_ / 64), 256>>>(vp, vth, vtl);

  // K1: E = K . Q^T   (M=N_, N=N_, K=64 per batch)
  mma_gemm<<<dim3(N_ / 128, N_ / 128, B_), 256, 65536>>>(
      kh, kl, qh, ql, ep, nullptr, D_, D_, N_, D_, (size_t)N_ * D_);
  // K2: softmax rows
  softmax_kernel<<<BN_, 256>>>(ep, ph, pl, scp, gamma);
  // K3: O = P . Vt^T  (M=N_, N=C_, K=N_ per batch), scaled by gamma/l
  mma_gemm<<<dim3(N_ / 128, C_ / 128, B_), 256, 65536>>>(
      ph, pl, vth, vtl, out, scp, N_, BN_, C_, N_, (size_t)N_);
}

// round 12
// speedup vs baseline: 3.1759x; 1.0874x over previous
#include <cuda_runtime.h>
#include <cuda_bf16.h>
#include <cstdint>

#define B_ 4
#define N_ 4096
#define C_ 512
#define D_ 64
#define BN_ (B_ * N_)

__device__ float g_e[(size_t)BN_ * N_];
__device__ float g_scale[BN_];
__device__ __nv_bfloat16 g_xh[(size_t)BN_ * C_], g_xl[(size_t)BN_ * C_];
__device__ __nv_bfloat16 g_qkh[(size_t)BN_ * 128], g_qkl[(size_t)BN_ * 128];
__device__ __nv_bfloat16 g_vth[(size_t)C_ * BN_], g_vtl[(size_t)C_ * BN_];
__device__ __nv_bfloat16 g_ph[(size_t)BN_ * N_], g_pl[(size_t)BN_ * N_];
__device__ __nv_bfloat16 g_wqkh[128 * C_], g_wqkl[128 * C_];
__device__ __nv_bfloat16 g_wvth[(size_t)C_ * C_], g_wvtl[(size_t)C_ * C_];

__device__ __forceinline__ uint32_t smem_u32(const void* p) {
  uint32_t a;
  asm("{ .reg .u64 t; cvta.to.shared.u64 t, %1; cvt.u32.u64 %0, t; }" : "=r"(a) : "l"(p));
  return a;
}
__device__ __forceinline__ void split2(float v, __nv_bfloat16& h, __nv_bfloat16& l) {
  h = __float2bfloat16(v);
  l = __float2bfloat16(v - __bfloat162float(h));
}

#define CP16(d, s) asm volatile("cp.async.cg.shared.global [%0], [%1], 16;" :: "r"(d), "l"(s))
#define CPCOMMIT() asm volatile("cp.async.commit_group;" ::: "memory")
#define CPWAIT1() asm volatile("cp.async.wait_group 1;" ::: "memory")

__device__ __forceinline__ void ldsm4(uint32_t* r, uint32_t a) {
  asm volatile("ldmatrix.sync.aligned.m8n8.x4.shared.b16 {%0,%1,%2,%3}, [%4];"
               : "=r"(r[0]), "=r"(r[1]), "=r"(r[2]), "=r"(r[3]) : "r"(a));
}
__device__ __forceinline__ void mma16816(float* d, const uint32_t* a, const uint32_t* b) {
  asm volatile(
      "mma.sync.aligned.m16n8k16.row.col.f32.bf16.bf16.f32 "
      "{%0,%1,%2,%3}, {%4,%5,%6,%7}, {%8,%9}, {%0,%1,%2,%3};"
      : "+f"(d[0]), "+f"(d[1]), "+f"(d[2]), "+f"(d[3])
      : "r"(a[0]), "r"(a[1]), "r"(a[2]), "r"(a[3]), "r"(b[0]), "r"(b[1]));
}

// split f32 -> hi/lo bf16 (used for x)
__global__ __launch_bounds__(256) void split_kernel(const float* __restrict__ s,
                                                    __nv_bfloat16* __restrict__ h,
                                                    __nv_bfloat16* __restrict__ l, int n4) {
  int i = blockIdx.x * 256 + threadIdx.x;
  if (i >= n4) return;
  float4 v = ((const float4*)s)[i];
  __nv_bfloat16 h0, h1, h2, h3, l0, l1, l2, l3;
  split2(v.x, h0, l0); split2(v.y, h1, l1); split2(v.z, h2, l2); split2(v.w, h3, l3);
  ((__nv_bfloat162*)h)[i * 2] = __nv_bfloat162(h0, h1);
  ((__nv_bfloat162*)h)[i * 2 + 1] = __nv_bfloat162(h2, h3);
  ((__nv_bfloat162*)l)[i * 2] = __nv_bfloat162(l0, l1);
  ((__nv_bfloat162*)l)[i * 2 + 1] = __nv_bfloat162(l2, l3);
}

// WqkT[d2][k] = d2<64 ? Wq[k][d2] : Wk[k][d2-64], split bf16. 128x512.
__global__ __launch_bounds__(256) void trans_split_wqk(const float* __restrict__ Wq,
                                                       const float* __restrict__ Wk,
                                                       __nv_bfloat16* __restrict__ th,
                                                       __nv_bfloat16* __restrict__ tl) {
  int idx = blockIdx.x * 256 + threadIdx.x;  // 65536 total
  int d2 = idx >> 9, k = idx & 511;
  float v = d2 < 64 ? Wq[k * 64 + d2] : Wk[k * 64 + (d2 - 64)];
  split2(v, th[idx], tl[idx]);
}
// WvT[c][k] = Wv[k][c], split bf16. 512x512.
__global__ __launch_bounds__(256) void trans_split_wv(const float* __restrict__ Wv,
                                                      __nv_bfloat16* __restrict__ th,
                                                      __nv_bfloat16* __restrict__ tl) {
  int idx = blockIdx.x * 256 + threadIdx.x;  // 262144 total
  int c = idx >> 9, k = idx & 511;
  split2(Wv[k * 512 + c], th[idx], tl[idx]);
}

// ---------------------------------------------------------------------------
// Generic split-bf16 GEMM via mma.sync: C[128x128 tile] = A . B^T, row.col.
// A rows: (b*N_ + i0 + r) * lda ; B rows: (n0 + r) * ldb + b * bStrB.
// 8 warps m64xn32; K chunks of 32; 2-stage cp.async double buffer (64KB smem).
// Epilogue: fp32 to Cm (xscale) OR split-bf16 to outH/outL when outH != null.
// ---------------------------------------------------------------------------
__global__ __launch_bounds__(256) void mma_gemm(
    const __nv_bfloat16* __restrict__ Ah, const __nv_bfloat16* __restrict__ Al,
    const __nv_bfloat16* __restrict__ Bh, const __nv_bfloat16* __restrict__ Bl,
    float* __restrict__ Cm, const float* __restrict__ scale,
    int lda, int ldb, int ldc, int K, size_t bStrB,
    __nv_bfloat16* __restrict__ outH, __nv_bfloat16* __restrict__ outL) {
  extern __shared__ char dsm[];
  const uint32_t sb = smem_u32(dsm);
  const int tid = threadIdx.x, lane = tid & 31, wid = tid >> 5;
  const int wm = wid & 1, wn = wid >> 1;
  const int b = blockIdx.z;
  const int i0 = blockIdx.x * 128, n0 = blockIdx.y * 128;
  const size_t bN = (size_t)b * N_;

  float acc[4][4][4];
#pragma unroll
  for (int mi = 0; mi < 4; ++mi)
#pragma unroll
    for (int nj = 0; nj < 4; ++nj)
#pragma unroll
      for (int e = 0; e < 4; ++e) acc[mi][nj][e] = 0.f;

  auto issue = [&](int kc) {
#pragma unroll
    for (int t = 0; t < 8; ++t) {
      int g = tid + t * 256, sub = g >> 9, gi = g & 511, row = gi >> 2, cc = gi & 3;
      uint32_t so = sb + (uint32_t)((kc & 1) * 32768 + sub * 8192 + row * 64 +
                                    ((cc ^ ((row >> 1) & 3)) << 4));
      const __nv_bfloat16* gp;
      if (sub < 2)
        gp = (sub == 0 ? Ah : Al) + (bN + i0 + row) * (size_t)lda + kc * 32 + cc * 8;
      else
        gp = (sub == 2 ? Bh : Bl) + (size_t)(n0 + row) * ldb + (size_t)b * bStrB +
             kc * 32 + cc * 8;
      CP16(so, gp);
    }
    CPCOMMIT();
  };

  const int chunks = K >> 5;
  issue(0);
  for (int kc = 0; kc < chunks; ++kc) {
    if (kc + 1 < chunks) issue(kc + 1); else CPCOMMIT();
    CPWAIT1();
    __syncthreads();
    const uint32_t st = sb + (uint32_t)((kc & 1) * 32768);
#pragma unroll
    for (int ks = 0; ks < 32; ks += 16) {
      uint32_t ah[4][4], al[4][4], bh[8], bl[8];
      const int rA = lane & 15, cA = (ks >> 3) + (lane >> 4);
      const int rB = (lane & 7) + ((lane >> 4) << 3), cB = (ks >> 3) + ((lane >> 3) & 1);
#pragma unroll
      for (int mi = 0; mi < 4; ++mi) {
        int row = wm * 64 + mi * 16 + rA;
        ldsm4(ah[mi], st + row * 64 + ((cA ^ ((row >> 1) & 3)) << 4));
      }
#pragma unroll
      for (int bf = 0; bf < 2; ++bf) {
        int row = wn * 32 + bf * 16 + rB;
        ldsm4(&bh[bf * 4], st + 16384 + row * 64 + ((cB ^ ((row >> 1) & 3)) << 4));
      }
#pragma unroll
      for (int mi = 0; mi < 4; ++mi)
#pragma unroll
        for (int nj = 0; nj < 4; ++nj) mma16816(acc[mi][nj], ah[mi], &bh[nj * 2]);
#pragma unroll
      for (int bf = 0; bf < 2; ++bf) {
        int row = wn * 32 + bf * 16 + rB;
        ldsm4(&bl[bf * 4], st + 24576 + row * 64 + ((cB ^ ((row >> 1) & 3)) << 4));
      }
#pragma unroll
      for (int mi = 0; mi < 4; ++mi)
#pragma unroll
        for (int nj = 0; nj < 4; ++nj) mma16816(acc[mi][nj], ah[mi], &bl[nj * 2]);
#pragma unroll
      for (int mi = 0; mi < 4; ++mi) {
        int row = wm * 64 + mi * 16 + rA;
        ldsm4(al[mi], st + 8192 + row * 64 + ((cA ^ ((row >> 1) & 3)) << 4));
      }
#pragma unroll
      for (int mi = 0; mi < 4; ++mi)
#pragma unroll
        for (int nj = 0; nj < 4; ++nj) mma16816(acc[mi][nj], al[mi], &bh[nj * 2]);
    }
    __syncthreads();
  }

#pragma unroll
  for (int mi = 0; mi < 4; ++mi) {
    int r0 = i0 + wm * 64 + mi * 16 + (lane >> 2);
    float s0 = scale ? scale[bN + r0] : 1.f;
    float s1 = scale ? scale[bN + r0 + 8] : 1.f;
#pragma unroll
    for (int nj = 0; nj < 4; ++nj) {
      int col = n0 + wn * 32 + nj * 8 + 2 * (lane & 3);
      size_t o0 = (bN + r0) * (size_t)ldc + col;
      size_t o1 = (bN + r0 + 8) * (size_t)ldc + col;
      if (outH) {
        __nv_bfloat16 h0, h1, h2, h3, l0, l1, l2, l3;
        split2(acc[mi][nj][0], h0, l0); split2(acc[mi][nj][1], h1, l1);
        split2(acc[mi][nj][2], h2, l2); split2(acc[mi][nj][3], h3, l3);
        ((__nv_bfloat162*)outH)[o0 >> 1] = __nv_bfloat162(h0, h1);
        ((__nv_bfloat162*)outH)[o1 >> 1] = __nv_bfloat162(h2, h3);
        ((__nv_bfloat162*)outL)[o0 >> 1] = __nv_bfloat162(l0, l1);
        ((__nv_bfloat162*)outL)[o1 >> 1] = __nv_bfloat162(l2, l3);
      } else {
        float2 v0 = {acc[mi][nj][0] * s0, acc[mi][nj][1] * s0};
        float2 v1 = {acc[mi][nj][2] * s1, acc[mi][nj][3] * s1};
        *(float2*)&Cm[o0] = v0;
        *(float2*)&Cm[o1] = v1;
      }
    }
  }
}

// K2: row softmax -> split-bf16 P, scale = gamma / rowsum
__global__ __launch_bounds__(256) void softmax_kernel(const float* __restrict__ E,
                                                      __nv_bfloat16* __restrict__ ph,
                                                      __nv_bfloat16* __restrict__ pl,
                                                      float* __restrict__ scale,
                                                      const float* __restrict__ gamma) {
  __shared__ float row[N_];
  __shared__ float red[8];
  __shared__ float bc;
  const int tid = threadIdx.x, wid = tid >> 5, lid = tid & 31;
  const size_t r = blockIdx.x;
  const float* er = E + r * N_;
  float lmax = -3.0e38f;
#pragma unroll
  for (int u = 0; u < 4; ++u) {
    int idx = tid + u * 256;
    float4 t = ((const float4*)er)[idx];
    ((float4*)row)[idx] = t;
    lmax = fmaxf(lmax, fmaxf(fmaxf(t.x, t.y), fmaxf(t.z, t.w)));
  }
#pragma unroll
  for (int s = 16; s > 0; s >>= 1) lmax = fmaxf(lmax, __shfl_xor_sync(~0u, lmax, s));
  if (lid == 0) red[wid] = lmax;
  __syncthreads();
  if (tid == 0) {
    float m = red[0];
#pragma unroll
    for (int i = 1; i < 8; ++i) m = fmaxf(m, red[i]);
    bc = m;
  }
  __syncthreads();
  const float m = bc;
  float lsum = 0.f;
#pragma unroll
  for (int u = 0; u < 4; ++u) {
    int idx = tid + u * 256;
    float4 t = ((const float4*)row)[idx];
    float p0 = __expf(t.x - m), p1 = __expf(t.y - m), p2 = __expf(t.z - m), p3 = __expf(t.w - m);
    lsum += (p0 + p1) + (p2 + p3);
    __nv_bfloat16 h0, h1, h2, h3, l0, l1, l2, l3;
    split2(p0, h0, l0); split2(p1, h1, l1); split2(p2, h2, l2); split2(p3, h3, l3);
    size_t o = (r * N_ + (size_t)idx * 4) >> 1;
    ((__nv_bfloat162*)ph)[o] = __nv_bfloat162(h0, h1);
    ((__nv_bfloat162*)ph)[o + 1] = __nv_bfloat162(h2, h3);
    ((__nv_bfloat162*)pl)[o] = __nv_bfloat162(l0, l1);
    ((__nv_bfloat162*)pl)[o + 1] = __nv_bfloat162(l2, l3);
  }
#pragma unroll
  for (int s = 16; s > 0; s >>= 1) lsum += __shfl_xor_sync(~0u, lsum, s);
  if (lid == 0) red[wid] = lsum;
  __syncthreads();
  if (tid == 0) {
    float t = 0.f;
#pragma unroll
    for (int i = 0; i < 8; ++i) t += red[i];
    scale[r] = gamma[0] / t;
  }
}

extern "C" void kernel_launch(void* const* d_in, const int* in_sizes, int n_in,
                              void* d_out, int out_size) {
  const float* x = (const float*)d_in[0];
  const float* Wq = (const float*)d_in[1];
  const float* Wk = (const float*)d_in[2];
  const float* Wv = (const float*)d_in[3];
  const float* gamma = (const float*)d_in[4];
  float* out = (float*)d_out;

  float *ep, *scp;
  __nv_bfloat16 *xh, *xl, *qkh, *qkl, *vth, *vtl, *ph, *pl, *wqh, *wql, *wvh, *wvl;
  cudaGetSymbolAddress((void**)&ep, g_e);
  cudaGetSymbolAddress((void**)&scp, g_scale);
  cudaGetSymbolAddress((void**)&xh, g_xh);
  cudaGetSymbolAddress((void**)&xl, g_xl);
  cudaGetSymbolAddress((void**)&qkh, g_qkh);
  cudaGetSymbolAddress((void**)&qkl, g_qkl);
  cudaGetSymbolAddress((void**)&vth, g_vth);
  cudaGetSymbolAddress((void**)&vtl, g_vtl);
  cudaGetSymbolAddress((void**)&ph, g_ph);
  cudaGetSymbolAddress((void**)&pl, g_pl);
  cudaGetSymbolAddress((void**)&wqh, g_wqkh);
  cudaGetSymbolAddress((void**)&wql, g_wqkl);
  cudaGetSymbolAddress((void**)&wvh, g_wvth);
  cudaGetSymbolAddress((void**)&wvl, g_wvtl);

  cudaFuncSetAttribute(mma_gemm, cudaFuncAttributeMaxDynamicSharedMemorySize, 65536);

  // Preprocess: split x, transpose+split weights
  split_kernel<<<BN_ * C_ / 4 / 256, 256>>>(x, xh, xl, BN_ * C_ / 4);
  trans_split_wqk<<<128 * C_ / 256, 256>>>(Wq, Wk, wqh, wql);
  trans_split_wv<<<C_ * C_ / 256, 256>>>(Wv, wvh, wvl);

  // Proj QK: qk[n][128] = x . WqkT^T  (M=BN, N=128, K=512), split-bf16 out
  mma_gemm<<<dim3(BN_ / 128, 1, 1), 256, 65536>>>(
      xh, xl, wqh, wql, nullptr, nullptr, C_, C_, 128, C_, 0, qkh, qkl);
  // Proj V^T: vt[c][n] = WvT . x^T  (M=512, N=BN, K=512), split-bf16 out
  mma_gemm<<<dim3(C_ / 128, BN_ / 128, 1), 256, 65536>>>(
      wvh, wvl, xh, xl, nullptr, nullptr, C_, C_, BN_, C_, 0, vth, vtl);

  // K1: E = K . Q^T   (M=N_, N=N_, K=64 per batch); k = qk cols 64.., q = cols 0..
  mma_gemm<<<dim3(N_ / 128, N_ / 128, B_), 256, 65536>>>(
      qkh + 64, qkl + 64, qkh, qkl, ep, nullptr, 128, 128, N_, D_,
      (size_t)N_ * 128, nullptr, nullptr);
  // K2: softmax rows
  softmax_kernel<<<BN_, 256>>>(ep, ph, pl, scp, gamma);
  // K3: O = P . Vt^T  (M=N_, N=C_, K=N_ per batch), scaled by gamma/l
  mma_gemm<<<dim3(N_ / 128, C_ / 128, B_), 256, 65536>>>(
      ph, pl, vth, vtl, out, scp, N_, BN_, C_, N_, (size_t)N_, nullptr, nullptr);
}

// round 13
// speedup vs baseline: 3.5555x; 1.1195x over previous
#include <cuda_runtime.h>
#include <cuda_bf16.h>
#include <cstdint>

#define B_ 4
#define N_ 4096
#define C_ 512
#define D_ 64
#define BN_ (B_ * N_)

__device__ float g_e[(size_t)BN_ * N_];
__device__ float g_scale[BN_];
__device__ __nv_bfloat16 g_xh[(size_t)BN_ * C_], g_xl[(size_t)BN_ * C_];
__device__ __nv_bfloat16 g_qkh[(size_t)BN_ * 128], g_qkl[(size_t)BN_ * 128];
__device__ __nv_bfloat16 g_vth[(size_t)C_ * BN_], g_vtl[(size_t)C_ * BN_];
__device__ __nv_bfloat16 g_ph[(size_t)BN_ * N_], g_pl[(size_t)BN_ * N_];
__device__ __nv_bfloat16 g_wqkh[128 * C_], g_wqkl[128 * C_];
__device__ __nv_bfloat16 g_wvth[(size_t)C_ * C_], g_wvtl[(size_t)C_ * C_];

__device__ __forceinline__ uint32_t smem_u32(const void* p) {
  uint32_t a;
  asm("{ .reg .u64 t; cvta.to.shared.u64 t, %1; cvt.u32.u64 %0, t; }" : "=r"(a) : "l"(p));
  return a;
}
__device__ __forceinline__ void split2(float v, __nv_bfloat16& h, __nv_bfloat16& l) {
  h = __float2bfloat16(v);
  l = __float2bfloat16(v - __bfloat162float(h));
}

#define CP16(d, s) asm volatile("cp.async.cg.shared.global [%0], [%1], 16;" :: "r"(d), "l"(s))
#define CPCOMMIT() asm volatile("cp.async.commit_group;" ::: "memory")
#define CPWAIT1() asm volatile("cp.async.wait_group 1;" ::: "memory")

__device__ __forceinline__ void ldsm4(uint32_t* r, uint32_t a) {
  asm volatile("ldmatrix.sync.aligned.m8n8.x4.shared.b16 {%0,%1,%2,%3}, [%4];"
               : "=r"(r[0]), "=r"(r[1]), "=r"(r[2]), "=r"(r[3]) : "r"(a));
}
__device__ __forceinline__ void mma16816(float* d, const uint32_t* a, const uint32_t* b) {
  asm volatile(
      "mma.sync.aligned.m16n8k16.row.col.f32.bf16.bf16.f32 "
      "{%0,%1,%2,%3}, {%4,%5,%6,%7}, {%8,%9}, {%0,%1,%2,%3};"
      : "+f"(d[0]), "+f"(d[1]), "+f"(d[2]), "+f"(d[3])
      : "r"(a[0]), "r"(a[1]), "r"(a[2]), "r"(a[3]), "r"(b[0]), "r"(b[1]));
}

// split f32 -> hi/lo bf16 (used for x)
__global__ __launch_bounds__(256) void split_kernel(const float* __restrict__ s,
                                                    __nv_bfloat16* __restrict__ h,
                                                    __nv_bfloat16* __restrict__ l, int n4) {
  int i = blockIdx.x * 256 + threadIdx.x;
  if (i >= n4) return;
  float4 v = ((const float4*)s)[i];
  __nv_bfloat16 h0, h1, h2, h3, l0, l1, l2, l3;
  split2(v.x, h0, l0); split2(v.y, h1, l1); split2(v.z, h2, l2); split2(v.w, h3, l3);
  ((__nv_bfloat162*)h)[i * 2] = __nv_bfloat162(h0, h1);
  ((__nv_bfloat162*)h)[i * 2 + 1] = __nv_bfloat162(h2, h3);
  ((__nv_bfloat162*)l)[i * 2] = __nv_bfloat162(l0, l1);
  ((__nv_bfloat162*)l)[i * 2 + 1] = __nv_bfloat162(l2, l3);
}

// WqkT[d2][k] = d2<64 ? Wq[k][d2] : Wk[k][d2-64], split bf16. 128x512.
__global__ __launch_bounds__(256) void trans_split_wqk(const float* __restrict__ Wq,
                                                       const float* __restrict__ Wk,
                                                       __nv_bfloat16* __restrict__ th,
                                                       __nv_bfloat16* __restrict__ tl) {
  int idx = blockIdx.x * 256 + threadIdx.x;  // 65536 total
  int d2 = idx >> 9, k = idx & 511;
  float v = d2 < 64 ? Wq[k * 64 + d2] : Wk[k * 64 + (d2 - 64)];
  split2(v, th[idx], tl[idx]);
}
// WvT[c][k] = Wv[k][c], split bf16. 512x512.
__global__ __launch_bounds__(256) void trans_split_wv(const float* __restrict__ Wv,
                                                      __nv_bfloat16* __restrict__ th,
                                                      __nv_bfloat16* __restrict__ tl) {
  int idx = blockIdx.x * 256 + threadIdx.x;  // 262144 total
  int c = idx >> 9, k = idx & 511;
  split2(Wv[k * 512 + c], th[idx], tl[idx]);
}

// ---------------------------------------------------------------------------
// Generic split-bf16 GEMM via mma.sync: C[128x128 tile] = A . B^T, row.col.
// A rows: (b*N_ + i0 + r) * lda ; B rows: (n0 + r) * ldb + b * bStrB.
// 8 warps m64xn32; K chunks of 32; 2-stage cp.async double buffer (64KB smem).
// __launch_bounds__(256, 2): cap 128 regs/thread -> 2 CTAs/SM (reg-limited at
// 138 regs we measured occ=12.5%, tensor=40%; co-residency hides barriers).
// Epilogue: fp32 to Cm (xscale) OR split-bf16 to outH/outL when outH != null.
// ---------------------------------------------------------------------------
__global__ __launch_bounds__(256, 2) void mma_gemm(
    const __nv_bfloat16* __restrict__ Ah, const __nv_bfloat16* __restrict__ Al,
    const __nv_bfloat16* __restrict__ Bh, const __nv_bfloat16* __restrict__ Bl,
    float* __restrict__ Cm, const float* __restrict__ scale,
    int lda, int ldb, int ldc, int K, size_t bStrB,
    __nv_bfloat16* __restrict__ outH, __nv_bfloat16* __restrict__ outL) {
  extern __shared__ char dsm[];
  const uint32_t sb = smem_u32(dsm);
  const int tid = threadIdx.x, lane = tid & 31, wid = tid >> 5;
  const int wm = wid & 1, wn = wid >> 1;
  const int b = blockIdx.z;
  const int i0 = blockIdx.x * 128, n0 = blockIdx.y * 128;
  const size_t bN = (size_t)b * N_;

  float acc[4][4][4];
#pragma unroll
  for (int mi = 0; mi < 4; ++mi)
#pragma unroll
    for (int nj = 0; nj < 4; ++nj)
#pragma unroll
      for (int e = 0; e < 4; ++e) acc[mi][nj][e] = 0.f;

  auto issue = [&](int kc) {
#pragma unroll
    for (int t = 0; t < 8; ++t) {
      int g = tid + t * 256, sub = g >> 9, gi = g & 511, row = gi >> 2, cc = gi & 3;
      uint32_t so = sb + (uint32_t)((kc & 1) * 32768 + sub * 8192 + row * 64 +
                                    ((cc ^ ((row >> 1) & 3)) << 4));
      const __nv_bfloat16* gp;
      if (sub < 2)
        gp = (sub == 0 ? Ah : Al) + (bN + i0 + row) * (size_t)lda + kc * 32 + cc * 8;
      else
        gp = (sub == 2 ? Bh : Bl) + (size_t)(n0 + row) * ldb + (size_t)b * bStrB +
             kc * 32 + cc * 8;
      CP16(so, gp);
    }
    CPCOMMIT();
  };

  const int chunks = K >> 5;
  issue(0);
  for (int kc = 0; kc < chunks; ++kc) {
    if (kc + 1 < chunks) issue(kc + 1); else CPCOMMIT();
    CPWAIT1();
    __syncthreads();
    const uint32_t st = sb + (uint32_t)((kc & 1) * 32768);
#pragma unroll
    for (int ks = 0; ks < 32; ks += 16) {
      uint32_t ah[4][4], al[4][4], bh[8], bl[8];
      const int rA = lane & 15, cA = (ks >> 3) + (lane >> 4);
      const int rB = (lane & 7) + ((lane >> 4) << 3), cB = (ks >> 3) + ((lane >> 3) & 1);
#pragma unroll
      for (int mi = 0; mi < 4; ++mi) {
        int row = wm * 64 + mi * 16 + rA;
        ldsm4(ah[mi], st + row * 64 + ((cA ^ ((row >> 1) & 3)) << 4));
      }
#pragma unroll
      for (int bf = 0; bf < 2; ++bf) {
        int row = wn * 32 + bf * 16 + rB;
        ldsm4(&bh[bf * 4], st + 16384 + row * 64 + ((cB ^ ((row >> 1) & 3)) << 4));
      }
#pragma unroll
      for (int mi = 0; mi < 4; ++mi)
#pragma unroll
        for (int nj = 0; nj < 4; ++nj) mma16816(acc[mi][nj], ah[mi], &bh[nj * 2]);
#pragma unroll
      for (int bf = 0; bf < 2; ++bf) {
        int row = wn * 32 + bf * 16 + rB;
        ldsm4(&bl[bf * 4], st + 24576 + row * 64 + ((cB ^ ((row >> 1) & 3)) << 4));
      }
#pragma unroll
      for (int mi = 0; mi < 4; ++mi)
#pragma unroll
        for (int nj = 0; nj < 4; ++nj) mma16816(acc[mi][nj], ah[mi], &bl[nj * 2]);
#pragma unroll
      for (int mi = 0; mi < 4; ++mi) {
        int row = wm * 64 + mi * 16 + rA;
        ldsm4(al[mi], st + 8192 + row * 64 + ((cA ^ ((row >> 1) & 3)) << 4));
      }
#pragma unroll
      for (int mi = 0; mi < 4; ++mi)
#pragma unroll
        for (int nj = 0; nj < 4; ++nj) mma16816(acc[mi][nj], al[mi], &bh[nj * 2]);
    }
    __syncthreads();
  }

#pragma unroll
  for (int mi = 0; mi < 4; ++mi) {
    int r0 = i0 + wm * 64 + mi * 16 + (lane >> 2);
    float s0 = scale ? scale[bN + r0] : 1.f;
    float s1 = scale ? scale[bN + r0 + 8] : 1.f;
#pragma unroll
    for (int nj = 0; nj < 4; ++nj) {
      int col = n0 + wn * 32 + nj * 8 + 2 * (lane & 3);
      size_t o0 = (bN + r0) * (size_t)ldc + col;
      size_t o1 = (bN + r0 + 8) * (size_t)ldc + col;
      if (outH) {
        __nv_bfloat16 h0, h1, h2, h3, l0, l1, l2, l3;
        split2(acc[mi][nj][0], h0, l0); split2(acc[mi][nj][1], h1, l1);
        split2(acc[mi][nj][2], h2, l2); split2(acc[mi][nj][3], h3, l3);
        ((__nv_bfloat162*)outH)[o0 >> 1] = __nv_bfloat162(h0, h1);
        ((__nv_bfloat162*)outH)[o1 >> 1] = __nv_bfloat162(h2, h3);
        ((__nv_bfloat162*)outL)[o0 >> 1] = __nv_bfloat162(l0, l1);
        ((__nv_bfloat162*)outL)[o1 >> 1] = __nv_bfloat162(l2, l3);
      } else {
        float2 v0 = {acc[mi][nj][0] * s0, acc[mi][nj][1] * s0};
        float2 v1 = {acc[mi][nj][2] * s1, acc[mi][nj][3] * s1};
        *(float2*)&Cm[o0] = v0;
        *(float2*)&Cm[o1] = v1;
      }
    }
  }
}

// K2: row softmax -> split-bf16 P, scale = gamma / rowsum
__global__ __launch_bounds__(256) void softmax_kernel(const float* __restrict__ E,
                                                      __nv_bfloat16* __restrict__ ph,
                                                      __nv_bfloat16* __restrict__ pl,
                                                      float* __restrict__ scale,
                                                      const float* __restrict__ gamma) {
  __shared__ float row[N_];
  __shared__ float red[8];
  __shared__ float bc;
  const int tid = threadIdx.x, wid = tid >> 5, lid = tid & 31;
  const size_t r = blockIdx.x;
  const float* er = E + r * N_;
  float lmax = -3.0e38f;
#pragma unroll
  for (int u = 0; u < 4; ++u) {
    int idx = tid + u * 256;
    float4 t = ((const float4*)er)[idx];
    ((float4*)row)[idx] = t;
    lmax = fmaxf(lmax, fmaxf(fmaxf(t.x, t.y), fmaxf(t.z, t.w)));
  }
#pragma unroll
  for (int s = 16; s > 0; s >>= 1) lmax = fmaxf(lmax, __shfl_xor_sync(~0u, lmax, s));
  if (lid == 0) red[wid] = lmax;
  __syncthreads();
  if (tid == 0) {
    float m = red[0];
#pragma unroll
    for (int i = 1; i < 8; ++i) m = fmaxf(m, red[i]);
    bc = m;
  }
  __syncthreads();
  const float m = bc;
  float lsum = 0.f;
#pragma unroll
  for (int u = 0; u < 4; ++u) {
    int idx = tid + u * 256;
    float4 t = ((const float4*)row)[idx];
    float p0 = __expf(t.x - m), p1 = __expf(t.y - m), p2 = __expf(t.z - m), p3 = __expf(t.w - m);
    lsum += (p0 + p1) + (p2 + p3);
    __nv_bfloat16 h0, h1, h2, h3, l0, l1, l2, l3;
    split2(p0, h0, l0); split2(p1, h1, l1); split2(p2, h2, l2); split2(p3, h3, l3);
    size_t o = (r * N_ + (size_t)idx * 4) >> 1;
    ((__nv_bfloat162*)ph)[o] = __nv_bfloat162(h0, h1);
    ((__nv_bfloat162*)ph)[o + 1] = __nv_bfloat162(h2, h3);
    ((__nv_bfloat162*)pl)[o] = __nv_bfloat162(l0, l1);
    ((__nv_bfloat162*)pl)[o + 1] = __nv_bfloat162(l2, l3);
  }
#pragma unroll
  for (int s = 16; s > 0; s >>= 1) lsum += __shfl_xor_sync(~0u, lsum, s);
  if (lid == 0) red[wid] = lsum;
  __syncthreads();
  if (tid == 0) {
    float t = 0.f;
#pragma unroll
    for (int i = 0; i < 8; ++i) t += red[i];
    scale[r] = gamma[0] / t;
  }
}

extern "C" void kernel_launch(void* const* d_in, const int* in_sizes, int n_in,
                              void* d_out, int out_size) {
  const float* x = (const float*)d_in[0];
  const float* Wq = (const float*)d_in[1];
  const float* Wk = (const float*)d_in[2];
  const float* Wv = (const float*)d_in[3];
  const float* gamma = (const float*)d_in[4];
  float* out = (float*)d_out;

  float *ep, *scp;
  __nv_bfloat16 *xh, *xl, *qkh, *qkl, *vth, *vtl, *ph, *pl, *wqh, *wql, *wvh, *wvl;
  cudaGetSymbolAddress((void**)&ep, g_e);
  cudaGetSymbolAddress((void**)&scp, g_scale);
  cudaGetSymbolAddress((void**)&xh, g_xh);
  cudaGetSymbolAddress((void**)&xl, g_xl);
  cudaGetSymbolAddress((void**)&qkh, g_qkh);
  cudaGetSymbolAddress((void**)&qkl, g_qkl);
  cudaGetSymbolAddress((void**)&vth, g_vth);
  cudaGetSymbolAddress((void**)&vtl, g_vtl);
  cudaGetSymbolAddress((void**)&ph, g_ph);
  cudaGetSymbolAddress((void**)&pl, g_pl);
  cudaGetSymbolAddress((void**)&wqh, g_wqkh);
  cudaGetSymbolAddress((void**)&wql, g_wqkl);
  cudaGetSymbolAddress((void**)&wvh, g_wvth);
  cudaGetSymbolAddress((void**)&wvl, g_wvtl);

  cudaFuncSetAttribute(mma_gemm, cudaFuncAttributeMaxDynamicSharedMemorySize, 65536);

  // Preprocess: split x, transpose+split weights
  split_kernel<<<BN_ * C_ / 4 / 256, 256>>>(x, xh, xl, BN_ * C_ / 4);
  trans_split_wqk<<<128 * C_ / 256, 256>>>(Wq, Wk, wqh, wql);
  trans_split_wv<<<C_ * C_ / 256, 256>>>(Wv, wvh, wvl);

  // Proj QK: qk[n][128] = x . WqkT^T  (M=BN, N=128, K=512), split-bf16 out
  mma_gemm<<<dim3(BN_ / 128, 1, 1), 256, 65536>>>(
      xh, xl, wqh, wql, nullptr, nullptr, C_, C_, 128, C_, 0, qkh, qkl);
  // Proj V^T: vt[c][n] = WvT . x^T  (M=512, N=BN, K=512), split-bf16 out
  mma_gemm<<<dim3(C_ / 128, BN_ / 128, 1), 256, 65536>>>(
      wvh, wvl, xh, xl, nullptr, nullptr, C_, C_, BN_, C_, 0, vth, vtl);

  // K1: E = K . Q^T   (M=N_, N=N_, K=64 per batch); k = qk cols 64.., q = cols 0..
  mma_gemm<<<dim3(N_ / 128, N_ / 128, B_), 256, 65536>>>(
      qkh + 64, qkl + 64, qkh, qkl, ep, nullptr, 128, 128, N_, D_,
      (size_t)N_ * 128, nullptr, nullptr);
  // K2: softmax rows
  softmax_kernel<<<BN_, 256>>>(ep, ph, pl, scp, gamma);
  // K3: O = P . Vt^T  (M=N_, N=C_, K=N_ per batch), scaled by gamma/l
  mma_gemm<<<dim3(N_ / 128, C_ / 128, B_), 256, 65536>>>(
      ph, pl, vth, vtl, out, scp, N_, BN_, C_, N_, (size_t)N_, nullptr, nullptr);
}